// round 6
// baseline (speedup 1.0000x reference)
#include <cuda_runtime.h>
#include <math.h>
#include <stdint.h>

#define CC 256
#define NN 2048
#define DD 65536
#define NE 64
#define ROUT 256
#define DECAYv 0.999f
#define GAMv 4.8828125e-7f
#define COMMITv 0.25f

__device__ float g_M[CC*CC];
__device__ float g_XX[CC*CC];
__device__ float g_G[NE*CC];
__device__ float g_A[NE*CC];
__device__ float g_Q[NE*NE];
__device__ float g_H[NE*NE];
__device__ double g_cnormd[NE], g_bcd[NE], g_bbd;
__device__ float g_s[NE];
__device__ float g_Wtb[CC];
__device__ float g_xsum[CC];
__device__ double g_accd[4];   // 0:S0  1:S1a  2:p  3:quad
__device__ float g_Y[NN*CC];
__device__ float g_resp[NN*NE];
__device__ int   g_cnt[NE];
__device__ int   g_tokn[NE*NN];
__device__ float g_tokr[NE*NN];
__device__ float g_Cnew[NE*DD];

__device__ __forceinline__ void mma8(float* c, const uint32_t* a, const uint32_t* b) {
    asm volatile("mma.sync.aligned.m16n8k8.row.col.f32.tf32.tf32.f32 "
        "{%0,%1,%2,%3}, {%4,%5,%6,%7}, {%8,%9}, {%0,%1,%2,%3};"
        : "+f"(c[0]), "+f"(c[1]), "+f"(c[2]), "+f"(c[3])
        : "r"(a[0]), "r"(a[1]), "r"(a[2]), "r"(a[3]), "r"(b[0]), "r"(b[1]));
}
__device__ __forceinline__ uint32_t fb(float x) { return __float_as_uint(x); }
__device__ __forceinline__ void hilo(float v, uint32_t& h, uint32_t& l) {
    uint32_t hb = __float_as_uint(v) & 0xFFFFE000u;
    h = hb;
    l = fb(v - __uint_as_float(hb));
}

// ================= zero =================
__global__ void k_zero(float* __restrict__ out) {
    int i = blockIdx.x * 256 + threadIdx.x;
    if (i < NN*ROUT) out[i] = 0.f;
    if (i < CC*CC) { g_M[i] = 0.f; g_XX[i] = 0.f; }
    if (i < NE*CC) { g_G[i]=0.f; g_A[i]=0.f; }
    if (i < NE*NE) { g_Q[i]=0.f; g_H[i]=0.f; }
    if (i < CC) { g_Wtb[i] = 0.f; g_xsum[i] = 0.f; }
    if (i < NE) { g_cnormd[i]=0.0; g_bcd[i]=0.0; g_s[i]=0.f; g_cnt[i]=0; }
    if (i < 4) g_accd[i] = 0.0;
    if (i == 4) g_bbd = 0.0;
}

// ================= phase 1: gram(M) | centW(G) | Y | gram(XX)+xsum =================
__global__ void __launch_bounds__(256) k_p1(const float* __restrict__ W,
                                            const float* __restrict__ cents,
                                            const float* __restrict__ bvec,
                                            const float* __restrict__ x,
                                            const float* __restrict__ pw1) {
    __shared__ __align__(16) char smp[43008];
    int b = blockIdx.x;
    int tid=threadIdx.x, warp=tid>>5, lane=tid&31, gid=lane>>2, tig=lane&3;

    if (b < 128 || b >= 384) {
        // ---- gram: dst = srcT @ src, block = 128 rows x 256 cols ----
        bool isXX = (b >= 384);
        float (*Ws)[260] = (float (*)[260])smp;
        int wm = warp>>2, wn = warp&3;
        const float* src; float* dst; int i0, d0, nch;
        if (!isXX) { i0 = (b&1)*128; d0 = (b>>1)*1024; nch = 32; src = W; dst = g_M; }
        else { int bb2 = b-384; i0 = (bb2&1)*128; d0 = (bb2>>1)*256; nch = 8; src = x; dst = g_XX; }
        float acc[4][8][4];
#pragma unroll
        for (int mt=0;mt<4;mt++)
#pragma unroll
            for (int nt=0;nt<8;nt++)
#pragma unroll
                for (int q=0;q<4;q++) acc[mt][nt][q]=0.f;
        float xacc = 0.f;

        for (int ch=0; ch<nch; ch++) {
            int drow = d0 + ch*32;
#pragma unroll
            for (int l=0;l<8;l++) {
                int idx = tid + l*256;
                int row = idx>>6, c4 = (idx&63)*4;
                float4 v = *(const float4*)(src + (size_t)(drow+row)*CC + c4);
                Ws[row][c4]=v.x; Ws[row][c4+1]=v.y; Ws[row][c4+2]=v.z; Ws[row][c4+3]=v.w;
            }
            __syncthreads();
            if (isXX && i0 == 0) {
#pragma unroll
                for (int row=0;row<32;row++) xacc += Ws[row][tid];
            }
            if (!isXX) {
#pragma unroll
                for (int k8=0;k8<4;k8++) {
                    int kb = k8*8;
                    uint32_t a[4][4];
#pragma unroll
                    for (int mt=0;mt<4;mt++) {
                        int ib = i0 + wm*64 + mt*16 + gid;
                        a[mt][0]=fb(Ws[kb+tig][ib]);   a[mt][1]=fb(Ws[kb+tig][ib+8]);
                        a[mt][2]=fb(Ws[kb+tig+4][ib]); a[mt][3]=fb(Ws[kb+tig+4][ib+8]);
                    }
#pragma unroll
                    for (int nt=0;nt<8;nt++) {
                        int jb = wn*64 + nt*8 + gid;
                        uint32_t bv[2] = { fb(Ws[kb+tig][jb]), fb(Ws[kb+tig+4][jb]) };
#pragma unroll
                        for (int mt=0;mt<4;mt++) mma8(acc[mt][nt], a[mt], bv);
                    }
                }
            } else {
#pragma unroll
                for (int k8=0;k8<4;k8++) {
                    int kb = k8*8;
                    uint32_t ah[4][4], al[4][4];
#pragma unroll
                    for (int mt=0;mt<4;mt++) {
                        int ib = i0 + wm*64 + mt*16 + gid;
                        hilo(Ws[kb+tig][ib],     ah[mt][0], al[mt][0]);
                        hilo(Ws[kb+tig][ib+8],   ah[mt][1], al[mt][1]);
                        hilo(Ws[kb+tig+4][ib],   ah[mt][2], al[mt][2]);
                        hilo(Ws[kb+tig+4][ib+8], ah[mt][3], al[mt][3]);
                    }
#pragma unroll
                    for (int nt=0;nt<8;nt++) {
                        int jb = wn*64 + nt*8 + gid;
                        uint32_t bh[2], bl[2];
                        hilo(Ws[kb+tig][jb],   bh[0], bl[0]);
                        hilo(Ws[kb+tig+4][jb], bh[1], bl[1]);
#pragma unroll
                        for (int mt=0;mt<4;mt++) {
                            mma8(acc[mt][nt], ah[mt], bh);
                            mma8(acc[mt][nt], ah[mt], bl);
                            mma8(acc[mt][nt], al[mt], bh);
                        }
                    }
                }
            }
            __syncthreads();
        }
#pragma unroll
        for (int mt=0;mt<4;mt++)
#pragma unroll
            for (int nt=0;nt<8;nt++) {
                int i = i0 + wm*64 + mt*16 + gid;
                int j = wn*64 + nt*8 + 2*tig;
                atomicAdd(&dst[i*CC+j],       acc[mt][nt][0]);
                atomicAdd(&dst[i*CC+j+1],     acc[mt][nt][1]);
                atomicAdd(&dst[(i+8)*CC+j],   acc[mt][nt][2]);
                atomicAdd(&dst[(i+8)*CC+j+1], acc[mt][nt][3]);
            }
        if (isXX && i0 == 0) atomicAdd(&g_xsum[tid], xacc);
    } else if (b < 256) {
        // ---- centW: G = Cents@W (hi/lo) + cnorm/bc/Wtb/bb ----
        float (*Cs)[36]  = (float (*)[36])smp;
        float (*Ws)[260] = (float (*)[260])(smp + 9216);
        float* bs        = (float*)(smp + 9216 + 33280);
        int blk = b - 128;
        int d0 = blk * 512;
        float acc[4][4][4];
#pragma unroll
        for (int mt=0;mt<4;mt++)
#pragma unroll
            for (int nt=0;nt<4;nt++)
#pragma unroll
                for (int q=0;q<4;q++) acc[mt][nt][q]=0.f;
        float accWtb=0.f, accCN=0.f, accBC=0.f, accBB=0.f;

        for (int ch=0; ch<16; ch++) {
            int dbase = d0 + ch*32;
#pragma unroll
            for (int l=0;l<2;l++) {
                int idx = tid + l*256;
                int e = idx>>3, q = (idx&7)*4;
                float4 v = *(const float4*)(cents + (size_t)e*DD + dbase + q);
                Cs[e][q]=v.x; Cs[e][q+1]=v.y; Cs[e][q+2]=v.z; Cs[e][q+3]=v.w;
            }
#pragma unroll
            for (int l=0;l<8;l++) {
                int idx = tid + l*256;
                int row = idx>>6, q = (idx&63)*4;
                float4 v = *(const float4*)(W + (size_t)(dbase+row)*CC + q);
                Ws[row][q]=v.x; Ws[row][q+1]=v.y; Ws[row][q+2]=v.z; Ws[row][q+3]=v.w;
            }
            if (tid < 32) bs[tid] = bvec[dbase + tid];
            __syncthreads();
            {
                float aw = 0.f;
                for (int k=0;k<32;k++) aw += bs[k]*Ws[k][tid];
                accWtb += aw;
            }
            if (tid < 64) {
                float cn=0.f, bc=0.f;
                for (int k=0;k<32;k++) { float c=Cs[tid][k]; cn+=c*c; bc+=c*bs[k]; }
                accCN += cn; accBC += bc;
            }
            if (tid == 64) {
                float sb=0.f;
                for (int k=0;k<32;k++) sb += bs[k]*bs[k];
                accBB += sb;
            }
#pragma unroll
            for (int k8=0;k8<4;k8++) {
                int kb = k8*8;
                uint32_t ah[4][4], al[4][4], bh[4][2], bl[4][2];
#pragma unroll
                for (int mt=0;mt<4;mt++) {
                    int e = mt*16 + gid;
                    hilo(Cs[e][kb+tig],     ah[mt][0], al[mt][0]);
                    hilo(Cs[e+8][kb+tig],   ah[mt][1], al[mt][1]);
                    hilo(Cs[e][kb+tig+4],   ah[mt][2], al[mt][2]);
                    hilo(Cs[e+8][kb+tig+4], ah[mt][3], al[mt][3]);
                }
#pragma unroll
                for (int nt=0;nt<4;nt++) {
                    int c = warp*32 + nt*8 + gid;
                    hilo(Ws[kb+tig][c],   bh[nt][0], bl[nt][0]);
                    hilo(Ws[kb+tig+4][c], bh[nt][1], bl[nt][1]);
                }
#pragma unroll
                for (int mt=0;mt<4;mt++)
#pragma unroll
                    for (int nt=0;nt<4;nt++) {
                        mma8(acc[mt][nt], ah[mt], bh[nt]);
                        mma8(acc[mt][nt], ah[mt], bl[nt]);
                        mma8(acc[mt][nt], al[mt], bh[nt]);
                    }
            }
            __syncthreads();
        }
#pragma unroll
        for (int mt=0;mt<4;mt++)
#pragma unroll
            for (int nt=0;nt<4;nt++) {
                int e = mt*16 + gid;
                int c = warp*32 + nt*8 + 2*tig;
                atomicAdd(&g_G[e*CC+c],       acc[mt][nt][0]);
                atomicAdd(&g_G[e*CC+c+1],     acc[mt][nt][1]);
                atomicAdd(&g_G[(e+8)*CC+c],   acc[mt][nt][2]);
                atomicAdd(&g_G[(e+8)*CC+c+1], acc[mt][nt][3]);
            }
        atomicAdd(&g_Wtb[tid], accWtb);
        if (tid < 64) { atomicAdd(&g_cnormd[tid], (double)accCN); atomicAdd(&g_bcd[tid], (double)accBC); }
        if (tid == 64) atomicAdd(&g_bbd, (double)accBB);
    } else {
        // ---- Y = X @ pw1^T  (hi/lo) ----
        float (*Xs)[36] = (float (*)[36])smp;
        float (*Bs)[36] = (float (*)[36])(smp + 9216);
        int yb = b - 256;
        int tok0 = (yb >> 2) * 64;
        int colgrp = yb & 3;
        const float* src = pw1 + (size_t)colgrp * 64 * CC;
        int wm = warp>>2, wn = warp&3;
        float acc[2][2][4];
#pragma unroll
        for (int mt=0;mt<2;mt++)
#pragma unroll
            for (int nt=0;nt<2;nt++)
#pragma unroll
                for (int q=0;q<4;q++) acc[mt][nt][q]=0.f;

        for (int ch=0; ch<8; ch++) {
            int kc = ch*32;
#pragma unroll
            for (int l=0;l<2;l++) {
                int idx = tid + l*256;
                int row = idx>>3, q = (idx&7)*4;
                float4 v = *(const float4*)(x + (size_t)(tok0+row)*CC + kc + q);
                Xs[row][q]=v.x; Xs[row][q+1]=v.y; Xs[row][q+2]=v.z; Xs[row][q+3]=v.w;
                float4 w = *(const float4*)(src + (size_t)row*CC + kc + q);
                Bs[row][q]=w.x; Bs[row][q+1]=w.y; Bs[row][q+2]=w.z; Bs[row][q+3]=w.w;
            }
            __syncthreads();
#pragma unroll
            for (int k8=0;k8<4;k8++) {
                int kb = k8*8;
                uint32_t ah[2][4], al[2][4], bh[2][2], bl[2][2];
#pragma unroll
                for (int mt=0;mt<2;mt++) {
                    int m0 = wm*32 + mt*16 + gid;
                    hilo(Xs[m0][kb+tig],     ah[mt][0], al[mt][0]);
                    hilo(Xs[m0+8][kb+tig],   ah[mt][1], al[mt][1]);
                    hilo(Xs[m0][kb+tig+4],   ah[mt][2], al[mt][2]);
                    hilo(Xs[m0+8][kb+tig+4], ah[mt][3], al[mt][3]);
                }
#pragma unroll
                for (int nt=0;nt<2;nt++) {
                    int nl = wn*16 + nt*8 + gid;
                    hilo(Bs[nl][kb+tig],   bh[nt][0], bl[nt][0]);
                    hilo(Bs[nl][kb+tig+4], bh[nt][1], bl[nt][1]);
                }
#pragma unroll
                for (int mt=0;mt<2;mt++)
#pragma unroll
                    for (int nt=0;nt<2;nt++) {
                        mma8(acc[mt][nt], ah[mt], bh[nt]);
                        mma8(acc[mt][nt], ah[mt], bl[nt]);
                        mma8(acc[mt][nt], al[mt], bh[nt]);
                    }
            }
            __syncthreads();
        }
#pragma unroll
        for (int mt=0;mt<2;mt++)
#pragma unroll
            for (int nt=0;nt<2;nt++) {
                int col = colgrp*64 + wn*16 + nt*8 + 2*tig;
#pragma unroll
                for (int rr=0;rr<2;rr++) {
                    int tok = tok0 + wm*32 + mt*16 + gid + rr*8;
                    g_Y[(size_t)tok*CC + col]   = acc[mt][nt][rr*2];
                    g_Y[(size_t)tok*CC + col+1] = acc[mt][nt][rr*2+1];
                }
            }
    }
}

// ================= xG = X@G^T (hi/lo) + fused softmax/S1a/binning =================
__global__ void __launch_bounds__(256) k_xg(const float* __restrict__ x,
                                            const float* __restrict__ u) {
    __shared__ float Xs[64][36];
    __shared__ float Bs[64][36];
    __shared__ float xgs[64][68];
    int tid=threadIdx.x, warp=tid>>5, lane=tid&31, gid=lane>>2, tig=lane&3;
    int wm = warp>>2, wn = warp&3;
    int tok0 = blockIdx.x * 64;
    float acc[2][2][4];
#pragma unroll
    for (int mt=0;mt<2;mt++)
#pragma unroll
        for (int nt=0;nt<2;nt++)
#pragma unroll
            for (int q=0;q<4;q++) acc[mt][nt][q]=0.f;

    for (int ch=0; ch<8; ch++) {
        int kc = ch*32;
#pragma unroll
        for (int l=0;l<2;l++) {
            int idx = tid + l*256;
            int row = idx>>3, q = (idx&7)*4;
            float4 v = *(const float4*)(x + (size_t)(tok0+row)*CC + kc + q);
            Xs[row][q]=v.x; Xs[row][q+1]=v.y; Xs[row][q+2]=v.z; Xs[row][q+3]=v.w;
            float4 w = *(const float4*)(g_G + (size_t)row*CC + kc + q);
            Bs[row][q]=w.x; Bs[row][q+1]=w.y; Bs[row][q+2]=w.z; Bs[row][q+3]=w.w;
        }
        __syncthreads();
#pragma unroll
        for (int k8=0;k8<4;k8++) {
            int kb = k8*8;
            uint32_t ah[2][4], al[2][4], bh[2][2], bl[2][2];
#pragma unroll
            for (int mt=0;mt<2;mt++) {
                int m0 = wm*32 + mt*16 + gid;
                hilo(Xs[m0][kb+tig],     ah[mt][0], al[mt][0]);
                hilo(Xs[m0+8][kb+tig],   ah[mt][1], al[mt][1]);
                hilo(Xs[m0][kb+tig+4],   ah[mt][2], al[mt][2]);
                hilo(Xs[m0+8][kb+tig+4], ah[mt][3], al[mt][3]);
            }
#pragma unroll
            for (int nt=0;nt<2;nt++) {
                int nl = wn*16 + nt*8 + gid;
                hilo(Bs[nl][kb+tig],   bh[nt][0], bl[nt][0]);
                hilo(Bs[nl][kb+tig+4], bh[nt][1], bl[nt][1]);
            }
#pragma unroll
            for (int mt=0;mt<2;mt++)
#pragma unroll
                for (int nt=0;nt<2;nt++) {
                    mma8(acc[mt][nt], ah[mt], bh[nt]);
                    mma8(acc[mt][nt], ah[mt], bl[nt]);
                    mma8(acc[mt][nt], al[mt], bh[nt]);
                }
        }
        __syncthreads();
    }
#pragma unroll
    for (int mt=0;mt<2;mt++)
#pragma unroll
        for (int nt=0;nt<2;nt++) {
            int col = wn*16 + nt*8 + 2*tig;
#pragma unroll
            for (int rr=0;rr<2;rr++) {
                int lt = wm*32 + mt*16 + gid + rr*8;
                xgs[lt][col]   = acc[mt][nt][rr*2];
                xgs[lt][col+1] = acc[mt][nt][rr*2+1];
            }
        }
    __syncthreads();
    // fused softmax + S1a + binning: warp handles 8 tokens
    float cn0 = (float)g_cnormd[lane], cn1 = (float)g_cnormd[lane+32];
    float bc0 = (float)g_bcd[lane],    bc1 = (float)g_bcd[lane+32];
    float s1acc = 0.f;
    for (int k=0;k<8;k++) {
        int lt = warp*8 + k;
        size_t n = tok0 + lt;
        float xg0 = xgs[lt][lane]    + bc0;
        float xg1 = xgs[lt][lane+32] + bc1;
        float l0 = 2.f*xg0 - cn0 - logf(-logf(u[n*NE+lane]));
        float l1 = 2.f*xg1 - cn1 - logf(-logf(u[n*NE+lane+32]));
        float m = fmaxf(l0, l1);
#pragma unroll
        for (int o=16;o>=1;o>>=1) m = fmaxf(m, __shfl_xor_sync(0xffffffffu, m, o));
        float ex0 = expf(l0 - m), ex1 = expf(l1 - m);
        float S = ex0 + ex1;
#pragma unroll
        for (int o=16;o>=1;o>>=1) S += __shfl_xor_sync(0xffffffffu, S, o);
        float r0 = ex0 / S, r1 = ex1 / S;
        g_resp[n*NE+lane]    = r0;
        g_resp[n*NE+lane+32] = r1;
        float s1 = r0*xg0 + r1*xg1;
#pragma unroll
        for (int o=16;o>=1;o>>=1) s1 += __shfl_xor_sync(0xffffffffu, s1, o);
        if (lane == 0) s1acc += s1;
        if (r0 > 1e-9f) {
            int p = atomicAdd(&g_cnt[lane], 1);
            g_tokn[lane*NN+p] = (int)n; g_tokr[lane*NN+p] = r0;
        }
        if (r1 > 1e-9f) {
            int p = atomicAdd(&g_cnt[lane+32], 1);
            g_tokn[(lane+32)*NN+p] = (int)n; g_tokr[(lane+32)*NN+p] = r1;
        }
    }
    if (lane == 0) atomicAdd(&g_accd[1], (double)s1acc);
}

// ================= A=R^T X, Q=R^T R (hi/lo), s =================
__global__ void __launch_bounds__(256) k_RX(const float* __restrict__ x) {
    __shared__ float Rs[32][68];
    __shared__ float Xs[32][260];
    int tid=threadIdx.x, warp=tid>>5, lane=tid&31, gid=lane>>2, tig=lane&3;
    int n0 = blockIdx.x * 64;
    float accA[4][4][4], accQ[4][4];
#pragma unroll
    for (int mt=0;mt<4;mt++) {
#pragma unroll
        for (int nt=0;nt<4;nt++)
#pragma unroll
            for (int q=0;q<4;q++) accA[mt][nt][q]=0.f;
#pragma unroll
        for (int q=0;q<4;q++) accQ[mt][q]=0.f;
    }
    float sp=0.f;

    for (int cchunk=0; cchunk<2; cchunk++) {
        int nb = n0 + cchunk*32;
#pragma unroll
        for (int l=0;l<8;l++) {
            int idx = tid + l*256;
            int row = idx>>6, e2 = idx&63;
            Rs[row][e2] = g_resp[(size_t)(nb+row)*NE + e2];
        }
#pragma unroll
        for (int l=0;l<8;l++) {
            int idx = tid + l*256;
            int row = idx>>6, q = (idx&63)*4;
            float4 v = *(const float4*)(x + (size_t)(nb+row)*CC + q);
            Xs[row][q]=v.x; Xs[row][q+1]=v.y; Xs[row][q+2]=v.z; Xs[row][q+3]=v.w;
        }
        __syncthreads();
        if (tid < 64) {
            for (int k=0;k<32;k++) sp += Rs[k][tid];
        }
#pragma unroll
        for (int k8=0;k8<4;k8++) {
            int kb = k8*8;
            uint32_t am[4][4], amh[4][4], aml[4][4];
#pragma unroll
            for (int mt=0;mt<4;mt++) {
                int m0 = mt*16;
                float v0 = Rs[kb+tig][m0+gid],   v1 = Rs[kb+tig][m0+gid+8];
                float v2 = Rs[kb+tig+4][m0+gid], v3 = Rs[kb+tig+4][m0+gid+8];
                am[mt][0]=fb(v0); am[mt][1]=fb(v1); am[mt][2]=fb(v2); am[mt][3]=fb(v3);
                hilo(v0, amh[mt][0], aml[mt][0]); hilo(v1, amh[mt][1], aml[mt][1]);
                hilo(v2, amh[mt][2], aml[mt][2]); hilo(v3, amh[mt][3], aml[mt][3]);
            }
#pragma unroll
            for (int nt=0;nt<4;nt++) {
                int c = warp*32 + nt*8 + gid;
                uint32_t bx[2] = { fb(Xs[kb+tig][c]), fb(Xs[kb+tig+4][c]) };
#pragma unroll
                for (int mt=0;mt<4;mt++) mma8(accA[mt][nt], am[mt], bx);
            }
            {
                int eq = warp*8 + gid;
                uint32_t bqh[2], bql[2];
                hilo(Rs[kb+tig][eq],   bqh[0], bql[0]);
                hilo(Rs[kb+tig+4][eq], bqh[1], bql[1]);
#pragma unroll
                for (int mt=0;mt<4;mt++) {
                    mma8(accQ[mt], amh[mt], bqh);
                    mma8(accQ[mt], amh[mt], bql);
                    mma8(accQ[mt], aml[mt], bqh);
                }
            }
        }
        __syncthreads();
    }
#pragma unroll
    for (int mt=0;mt<4;mt++) {
#pragma unroll
        for (int nt=0;nt<4;nt++) {
            int e = mt*16 + gid;
            int c = warp*32 + nt*8 + 2*tig;
            atomicAdd(&g_A[e*CC+c],        accA[mt][nt][0]);
            atomicAdd(&g_A[e*CC+c+1],      accA[mt][nt][1]);
            atomicAdd(&g_A[(e+8)*CC+c],    accA[mt][nt][2]);
            atomicAdd(&g_A[(e+8)*CC+c+1],  accA[mt][nt][3]);
        }
        int e = mt*16 + gid;
        int eq = warp*8 + 2*tig;
        atomicAdd(&g_Q[e*NE+eq],       accQ[mt][0]);
        atomicAdd(&g_Q[e*NE+eq+1],     accQ[mt][1]);
        atomicAdd(&g_Q[(e+8)*NE+eq],   accQ[mt][2]);
        atomicAdd(&g_Q[(e+8)*NE+eq+1], accQ[mt][3]);
    }
    if (tid < 64) atomicAdd(&g_s[tid], sp);
}

// ================= Cnew = decay*Cents + gam*(A@W^T + s b^T) =================
__global__ void __launch_bounds__(256) k_cnew(const float* __restrict__ W,
                                              const float* __restrict__ cents,
                                              const float* __restrict__ bvec) {
    __shared__ float As[64][36];
    __shared__ float Ws[128][36];
    __shared__ float ss[64];
    int tid=threadIdx.x, warp=tid>>5, lane=tid&31, gid=lane>>2, tig=lane&3;
    int d0 = blockIdx.x * 128;
    if (tid < 64) ss[tid] = g_s[tid];
    float acc[4][2][4];
#pragma unroll
    for (int mt=0;mt<4;mt++)
#pragma unroll
        for (int nt=0;nt<2;nt++)
#pragma unroll
            for (int q=0;q<4;q++) acc[mt][nt][q]=0.f;

    for (int ch=0; ch<8; ch++) {
        int kc = ch*32;
#pragma unroll
        for (int l=0;l<2;l++) {
            int idx = tid + l*256;
            int row = idx>>3, q = (idx&7)*4;
            float4 v = *(const float4*)(g_A + (size_t)row*CC + kc + q);
            As[row][q]=v.x; As[row][q+1]=v.y; As[row][q+2]=v.z; As[row][q+3]=v.w;
        }
#pragma unroll
        for (int l=0;l<4;l++) {
            int idx = tid + l*256;
            int row = idx>>3, q = (idx&7)*4;
            float4 v = *(const float4*)(W + (size_t)(d0+row)*CC + kc + q);
            Ws[row][q]=v.x; Ws[row][q+1]=v.y; Ws[row][q+2]=v.z; Ws[row][q+3]=v.w;
        }
        __syncthreads();
#pragma unroll
        for (int k8=0;k8<4;k8++) {
            int kb = k8*8;
            uint32_t a[4][4], b[2][2];
#pragma unroll
            for (int mt=0;mt<4;mt++) {
                int e = mt*16 + gid;
                a[mt][0]=fb(As[e][kb+tig]);   a[mt][1]=fb(As[e+8][kb+tig]);
                a[mt][2]=fb(As[e][kb+tig+4]); a[mt][3]=fb(As[e+8][kb+tig+4]);
            }
#pragma unroll
            for (int nt=0;nt<2;nt++) {
                int dl = warp*16 + nt*8 + gid;
                b[nt][0]=fb(Ws[dl][kb+tig]); b[nt][1]=fb(Ws[dl][kb+tig+4]);
            }
#pragma unroll
            for (int mt=0;mt<4;mt++)
#pragma unroll
                for (int nt=0;nt<2;nt++) mma8(acc[mt][nt], a[mt], b[nt]);
        }
        __syncthreads();
    }
#pragma unroll
    for (int mt=0;mt<4;mt++)
#pragma unroll
        for (int nt=0;nt<2;nt++) {
            int e = mt*16 + gid;
            int d = d0 + warp*16 + nt*8 + 2*tig;
            float b0 = bvec[d], b1 = bvec[d+1];
            g_Cnew[(size_t)e*DD+d]       = DECAYv*cents[(size_t)e*DD+d]       + GAMv*(acc[mt][nt][0] + ss[e]*b0);
            g_Cnew[(size_t)e*DD+d+1]     = DECAYv*cents[(size_t)e*DD+d+1]     + GAMv*(acc[mt][nt][1] + ss[e]*b1);
            g_Cnew[(size_t)(e+8)*DD+d]   = DECAYv*cents[(size_t)(e+8)*DD+d]   + GAMv*(acc[mt][nt][2] + ss[e+8]*b0);
            g_Cnew[(size_t)(e+8)*DD+d+1] = DECAYv*cents[(size_t)(e+8)*DD+d+1] + GAMv*(acc[mt][nt][3] + ss[e+8]*b1);
        }
}

// ================= tail: H (hi/lo) | binned output GEMM =================
__global__ void __launch_bounds__(256) k_tail(float* __restrict__ out) {
    __shared__ __align__(16) char smp[70400];
    int b = blockIdx.x;
    int tid=threadIdx.x, warp=tid>>5, lane=tid&31, gid=lane>>2, tig=lane&3;
    if (b < 128) {
        float (*Cs)[36] = (float (*)[36])smp;
        int d0 = b * 512;
        float acc[4][4];
#pragma unroll
        for (int mt=0;mt<4;mt++)
#pragma unroll
            for (int q=0;q<4;q++) acc[mt][q]=0.f;

        for (int ch=0; ch<16; ch++) {
            int dbase = d0 + ch*32;
#pragma unroll
            for (int l=0;l<2;l++) {
                int idx = tid + l*256;
                int e = idx>>3, q = (idx&7)*4;
                float4 v = *(const float4*)(g_Cnew + (size_t)e*DD + dbase + q);
                Cs[e][q]=v.x; Cs[e][q+1]=v.y; Cs[e][q+2]=v.z; Cs[e][q+3]=v.w;
            }
            __syncthreads();
#pragma unroll
            for (int k8=0;k8<4;k8++) {
                int kb = k8*8;
                uint32_t ah[4][4], al[4][4], bh[2], bl[2];
#pragma unroll
                for (int mt=0;mt<4;mt++) {
                    int e = mt*16 + gid;
                    hilo(Cs[e][kb+tig],     ah[mt][0], al[mt][0]);
                    hilo(Cs[e+8][kb+tig],   ah[mt][1], al[mt][1]);
                    hilo(Cs[e][kb+tig+4],   ah[mt][2], al[mt][2]);
                    hilo(Cs[e+8][kb+tig+4], ah[mt][3], al[mt][3]);
                }
                int n0 = warp*8 + gid;
                hilo(Cs[n0][kb+tig],   bh[0], bl[0]);
                hilo(Cs[n0][kb+tig+4], bh[1], bl[1]);
#pragma unroll
                for (int mt=0;mt<4;mt++) {
                    mma8(acc[mt], ah[mt], bh);
                    mma8(acc[mt], ah[mt], bl);
                    mma8(acc[mt], al[mt], bh);
                }
            }
            __syncthreads();
        }
#pragma unroll
        for (int mt=0;mt<4;mt++) {
            int e = mt*16 + gid;
            int n = warp*8 + 2*tig;
            atomicAdd(&g_H[e*NE+n],       acc[mt][0]);
            atomicAdd(&g_H[e*NE+n+1],     acc[mt][1]);
            atomicAdd(&g_H[(e+8)*NE+n],   acc[mt][2]);
            atomicAdd(&g_H[(e+8)*NE+n+1], acc[mt][3]);
        }
    } else {
        int idx0 = b - 128;
        int e = idx0 & 63;
        int cnt = g_cnt[e];
        int a0 = (idx0 >> 6) * 32;
        if (a0 >= cnt) return;
        float (*ys)[260] = (float (*)[260])smp;
        float (*Cw)[36]  = (float (*)[36])(smp + 33280);
        int* stok        = (int*)(smp + 33280 + 36864);
        int wm = warp>>2, wn = warp&3;
#pragma unroll
        for (int l=0;l<8;l++) {
            int idx = tid + l*256;
            int row = idx >> 6, q = idx & 63;
            int aa = a0 + row;
            float r = 0.f; int n = 0;
            float4 v = make_float4(0.f,0.f,0.f,0.f);
            if (aa < cnt) {
                n = g_tokn[e*NN+aa]; r = g_tokr[e*NN+aa];
                v = *(const float4*)(g_Y + (size_t)n*CC + q*4);
            }
            ys[row][q*4]=r*v.x; ys[row][q*4+1]=r*v.y; ys[row][q*4+2]=r*v.z; ys[row][q*4+3]=r*v.w;
            if (q == 0) stok[row] = n;
        }
        __syncthreads();
        float acc[8][4];
#pragma unroll
        for (int nt=0;nt<8;nt++)
#pragma unroll
            for (int q=0;q<4;q++) acc[nt][q]=0.f;

        for (int ch=0; ch<8; ch++) {
            int kc = ch*32;
#pragma unroll
            for (int l=0;l<8;l++) {
                int idx = tid + l*256;
                int row = idx >> 3, q = (idx & 7)*4;
                float4 v = *(const float4*)(g_Cnew + (size_t)e*DD + (size_t)row*CC + kc + q);
                Cw[row][q]=v.x; Cw[row][q+1]=v.y; Cw[row][q+2]=v.z; Cw[row][q+3]=v.w;
            }
            __syncthreads();
#pragma unroll
            for (int k8=0;k8<4;k8++) {
                int kb = k8*8;
                uint32_t ah[4], al[4];
                int m0 = wm*16 + gid;
                hilo(ys[m0][kc+kb+tig],     ah[0], al[0]);
                hilo(ys[m0+8][kc+kb+tig],   ah[1], al[1]);
                hilo(ys[m0][kc+kb+tig+4],   ah[2], al[2]);
                hilo(ys[m0+8][kc+kb+tig+4], ah[3], al[3]);
#pragma unroll
                for (int nt=0;nt<8;nt++) {
                    int nc = wn*64 + nt*8 + gid;
                    uint32_t bh[2], bl[2];
                    hilo(Cw[nc][kb+tig],   bh[0], bl[0]);
                    hilo(Cw[nc][kb+tig+4], bh[1], bl[1]);
                    mma8(acc[nt], ah, bh);
                    mma8(acc[nt], ah, bl);
                    mma8(acc[nt], al, bh);
                }
            }
            __syncthreads();
        }
        int t0 = wm*16 + gid;
        int r0 = stok[t0], r1 = stok[t0+8];
#pragma unroll
        for (int nt=0;nt<8;nt++) {
            int i = wn*64 + nt*8 + 2*tig;
            atomicAdd(out + (size_t)r0*ROUT + i,   acc[nt][0]);
            atomicAdd(out + (size_t)r0*ROUT + i+1, acc[nt][1]);
            atomicAdd(out + (size_t)r1*ROUT + i,   acc[nt][2]);
            atomicAdd(out + (size_t)r1*ROUT + i+1, acc[nt][3]);
        }
    }
}

// ================= fin: bias | loss partials =================
__global__ void k_fin(float* __restrict__ out, const float* __restrict__ pwB) {
    int b = blockIdx.x, tid = threadIdx.x;
    if (b < NN) {
        out[(size_t)b*ROUT + tid] += pwB[tid];
        return;
    }
    int lb = b - NN;   // 0..7
    __shared__ float As[256];
    __shared__ float red[256];
    double pacc = 0.0;
    for (int ei=0; ei<8; ei++) {
        int e = lb*8 + ei;
        __syncthreads();
        As[tid] = g_A[e*CC + tid];
        __syncthreads();
        float am = 0.f;
        for (int c2=0;c2<256;c2++) am += As[c2] * g_M[c2*CC + tid];
        float v = am*As[tid] + 2.f*g_s[e]*(As[tid]*g_Wtb[tid]);
        red[tid] = v; __syncthreads();
        for (int s=128;s>=1;s>>=1) { if (tid<s) red[tid]+=red[tid+s]; __syncthreads(); }
        if (tid == 0) pacc += (double)red[0] + (double)g_bbd*(double)g_s[e]*(double)g_s[e];
    }
    if (tid == 0) atomicAdd(&g_accd[2], pacc);
    __syncthreads();
    // S0 part: <XX, M> rows lb*32..+32
    float s0p = 0.f;
    for (int idx = tid; idx < 32*256; idx += 256) {
        int i = lb*32 + (idx >> 8);
        int j = idx & 255;
        s0p += g_XX[i*CC+j] * g_M[i*CC+j];
    }
    red[tid] = s0p; __syncthreads();
    for (int s=128;s>=1;s>>=1) { if (tid<s) red[tid]+=red[tid+s]; __syncthreads(); }
    if (tid == 0) atomicAdd(&g_accd[0], (double)red[0]);
    __syncthreads();
    if (lb == 0) {
        red[tid] = g_xsum[tid] * g_Wtb[tid]; __syncthreads();
        for (int s=128;s>=1;s>>=1) { if (tid<s) red[tid]+=red[tid+s]; __syncthreads(); }
        if (tid == 0) atomicAdd(&g_accd[0], 2.0*(double)red[0] + (double)NN*g_bbd);
        __syncthreads();
    }
    // quad part: <H, Q> rows lb*8..+8
    float qp = 0.f;
    for (int idx = tid; idx < 8*64; idx += 256) {
        int r = lb*8 + (idx >> 6);
        int c2 = idx & 63;
        qp += g_H[r*NE+c2] * g_Q[r*NE+c2];
    }
    red[tid] = qp; __syncthreads();
    for (int s=128;s>=1;s>>=1) { if (tid<s) red[tid]+=red[tid+s]; __syncthreads(); }
    if (tid == 0) atomicAdd(&g_accd[3], (double)red[0]);
}

// ================= last: write loss tail =================
__global__ void k_last(float* __restrict__ out, int out_size) {
    double S1 = (double)DECAYv * g_accd[1] + (double)GAMv * g_accd[2];
    float loss = (float)((double)COMMITv * (g_accd[0] - 2.0*S1 + g_accd[3]) / ((double)NN * (double)DD));
    for (int i = NN*ROUT + threadIdx.x; i < out_size; i += 256) out[i] = loss;
}

extern "C" void kernel_launch(void* const* d_in, const int* in_sizes, int n_in,
                              void* d_out, int out_size) {
    const float* x     = (const float*)d_in[0];
    const float* u     = (const float*)d_in[1];
    const float* W     = (const float*)d_in[2];
    const float* bvec  = (const float*)d_in[3];
    const float* pw1   = (const float*)d_in[4];
    const float* pwB   = (const float*)d_in[5];
    const float* cents = (const float*)d_in[6];
    float* out = (float*)d_out;

    k_zero<<<2048, 256>>>(out);
    k_p1<<<400, 256>>>(W, cents, bvec, x, pw1);
    k_xg<<<32, 256>>>(x, u);
    k_RX<<<32, 256>>>(x);
    k_cnew<<<512, 256>>>(W, cents, bvec);
    k_tail<<<128 + 64*64, 256>>>(out);
    k_fin<<<NN + 8, 256>>>(out, pwB);
    k_last<<<1, 256>>>(out, out_size);
}

// round 7
// speedup vs baseline: 1.2415x; 1.2415x over previous
#include <cuda_runtime.h>
#include <math.h>
#include <stdint.h>

#define CC 256
#define NN 2048
#define DD 65536
#define NE 64
#define ROUT 256
#define DECAYv 0.999f
#define GAMv 4.8828125e-7f
#define COMMITv 0.25f

__device__ float g_M[CC*CC];
__device__ float g_G[NE*CC];
__device__ float g_A[NE*CC];
__device__ float g_B2[NE*CC];
__device__ float g_Q[NE*NE];
__device__ float g_H[NE*NE];
__device__ double g_cnormd[NE], g_bcd[NE], g_bbd;
__device__ float g_s[NE], g_t[NE];
__device__ float g_Wtb[CC];
__device__ double g_accd[2];      // 0: S0, 1: S1a
__device__ float g_XM[NN*CC];
__device__ float g_Y[NN*CC];
__device__ float g_xWtb[NN];
__device__ float g_resp[NN*NE];
__device__ int   g_cnt[NE];
__device__ int   g_tokn[NE*NN];
__device__ float g_tokr[NE*NN];
__device__ float g_Cnew[NE*DD];

__device__ __forceinline__ void mma8(float* c, const uint32_t* a, const uint32_t* b) {
    asm volatile("mma.sync.aligned.m16n8k8.row.col.f32.tf32.tf32.f32 "
        "{%0,%1,%2,%3}, {%4,%5,%6,%7}, {%8,%9}, {%0,%1,%2,%3};"
        : "+f"(c[0]), "+f"(c[1]), "+f"(c[2]), "+f"(c[3])
        : "r"(a[0]), "r"(a[1]), "r"(a[2]), "r"(a[3]), "r"(b[0]), "r"(b[1]));
}
__device__ __forceinline__ uint32_t fb(float x) { return __float_as_uint(x); }
__device__ __forceinline__ void hilo(float v, uint32_t& h, uint32_t& l) {
    uint32_t hb = __float_as_uint(v) & 0xFFFFE000u;
    h = hb;
    l = fb(v - __uint_as_float(hb));
}

// ================= zero =================
__global__ void k_zero(float* __restrict__ out) {
    int i = blockIdx.x * 256 + threadIdx.x;
    if (i < NN*ROUT) out[i] = 0.f;
    if (i < CC*CC) g_M[i] = 0.f;
    if (i < NE*CC) { g_G[i]=0.f; g_A[i]=0.f; g_B2[i]=0.f; }
    if (i < NE*NE) { g_Q[i]=0.f; g_H[i]=0.f; }
    if (i < CC) g_Wtb[i] = 0.f;
    if (i < NE) { g_cnormd[i]=0.0; g_bcd[i]=0.0; g_s[i]=0.f; g_t[i]=0.f; g_cnt[i]=0; }
    if (i < 2) g_accd[i] = 0.0;
    if (i == 2) g_bbd = 0.0;
}

// ================= phase 1: gram(M, 128 blks) | centW | Y =================
__global__ void __launch_bounds__(256) k_p1(const float* __restrict__ W,
                                            const float* __restrict__ cents,
                                            const float* __restrict__ bvec,
                                            const float* __restrict__ x,
                                            const float* __restrict__ pw1) {
    __shared__ __align__(16) char smp[43008];
    int b = blockIdx.x;
    int tid=threadIdx.x, warp=tid>>5, lane=tid&31, gid=lane>>2, tig=lane&3;

    if (b < 128) {
        // ---- gram: M = W^T W, block = 128 rows x 256 cols, splitK (128 blocks x 32 chunks) ----
        float (*Ws)[260] = (float (*)[260])smp;
        int wm = warp>>2, wn = warp&3;
        int i0 = (b & 1) * 128;
        int d0 = (b >> 1) * 1024;
        float acc[4][8][4];
#pragma unroll
        for (int mt=0;mt<4;mt++)
#pragma unroll
            for (int nt=0;nt<8;nt++)
#pragma unroll
                for (int q=0;q<4;q++) acc[mt][nt][q]=0.f;

        for (int ch=0; ch<32; ch++) {
            int drow = d0 + ch*32;
#pragma unroll
            for (int l=0;l<8;l++) {
                int idx = tid + l*256;
                int row = idx>>6, c4 = (idx&63)*4;
                float4 v = *(const float4*)(W + (size_t)(drow+row)*CC + c4);
                Ws[row][c4]=v.x; Ws[row][c4+1]=v.y; Ws[row][c4+2]=v.z; Ws[row][c4+3]=v.w;
            }
            __syncthreads();
#pragma unroll
            for (int k8=0;k8<4;k8++) {
                int kb = k8*8;
                uint32_t a[4][4];
#pragma unroll
                for (int mt=0;mt<4;mt++) {
                    int ib = i0 + wm*64 + mt*16 + gid;
                    a[mt][0]=fb(Ws[kb+tig][ib]);   a[mt][1]=fb(Ws[kb+tig][ib+8]);
                    a[mt][2]=fb(Ws[kb+tig+4][ib]); a[mt][3]=fb(Ws[kb+tig+4][ib+8]);
                }
#pragma unroll
                for (int nt=0;nt<8;nt++) {
                    int jb = wn*64 + nt*8 + gid;
                    uint32_t bv[2] = { fb(Ws[kb+tig][jb]), fb(Ws[kb+tig+4][jb]) };
#pragma unroll
                    for (int mt=0;mt<4;mt++) mma8(acc[mt][nt], a[mt], bv);
                }
            }
            __syncthreads();
        }
#pragma unroll
        for (int mt=0;mt<4;mt++)
#pragma unroll
            for (int nt=0;nt<8;nt++) {
                int i = i0 + wm*64 + mt*16 + gid;
                int j = wn*64 + nt*8 + 2*tig;
                atomicAdd(&g_M[i*CC+j],       acc[mt][nt][0]);
                atomicAdd(&g_M[i*CC+j+1],     acc[mt][nt][1]);
                atomicAdd(&g_M[(i+8)*CC+j],   acc[mt][nt][2]);
                atomicAdd(&g_M[(i+8)*CC+j+1], acc[mt][nt][3]);
            }
    } else if (b < 256) {
        // ---- centW: G = Cents@W (hi/lo) + cnorm/bc/Wtb/bb ----
        float (*Cs)[36]  = (float (*)[36])smp;
        float (*Ws)[260] = (float (*)[260])(smp + 9216);
        float* bs        = (float*)(smp + 9216 + 33280);
        int blk = b - 128;
        int d0 = blk * 512;
        float acc[4][4][4];
#pragma unroll
        for (int mt=0;mt<4;mt++)
#pragma unroll
            for (int nt=0;nt<4;nt++)
#pragma unroll
                for (int q=0;q<4;q++) acc[mt][nt][q]=0.f;
        float accWtb=0.f, accCN=0.f, accBC=0.f, accBB=0.f;

        for (int ch=0; ch<16; ch++) {
            int dbase = d0 + ch*32;
#pragma unroll
            for (int l=0;l<2;l++) {
                int idx = tid + l*256;
                int e = idx>>3, q = (idx&7)*4;
                float4 v = *(const float4*)(cents + (size_t)e*DD + dbase + q);
                Cs[e][q]=v.x; Cs[e][q+1]=v.y; Cs[e][q+2]=v.z; Cs[e][q+3]=v.w;
            }
#pragma unroll
            for (int l=0;l<8;l++) {
                int idx = tid + l*256;
                int row = idx>>6, q = (idx&63)*4;
                float4 v = *(const float4*)(W + (size_t)(dbase+row)*CC + q);
                Ws[row][q]=v.x; Ws[row][q+1]=v.y; Ws[row][q+2]=v.z; Ws[row][q+3]=v.w;
            }
            if (tid < 32) bs[tid] = bvec[dbase + tid];
            __syncthreads();
            {
                float aw = 0.f;
                for (int k=0;k<32;k++) aw += bs[k]*Ws[k][tid];
                accWtb += aw;
            }
            if (tid < 64) {
                float cn=0.f, bc=0.f;
                for (int k=0;k<32;k++) { float c=Cs[tid][k]; cn+=c*c; bc+=c*bs[k]; }
                accCN += cn; accBC += bc;
            }
            if (tid == 64) {
                float sb=0.f;
                for (int k=0;k<32;k++) sb += bs[k]*bs[k];
                accBB += sb;
            }
#pragma unroll
            for (int k8=0;k8<4;k8++) {
                int kb = k8*8;
                uint32_t ah[4][4], al[4][4], bh[4][2], bl[4][2];
#pragma unroll
                for (int mt=0;mt<4;mt++) {
                    int e = mt*16 + gid;
                    hilo(Cs[e][kb+tig],     ah[mt][0], al[mt][0]);
                    hilo(Cs[e+8][kb+tig],   ah[mt][1], al[mt][1]);
                    hilo(Cs[e][kb+tig+4],   ah[mt][2], al[mt][2]);
                    hilo(Cs[e+8][kb+tig+4], ah[mt][3], al[mt][3]);
                }
#pragma unroll
                for (int nt=0;nt<4;nt++) {
                    int c = warp*32 + nt*8 + gid;
                    hilo(Ws[kb+tig][c],   bh[nt][0], bl[nt][0]);
                    hilo(Ws[kb+tig+4][c], bh[nt][1], bl[nt][1]);
                }
#pragma unroll
                for (int mt=0;mt<4;mt++)
#pragma unroll
                    for (int nt=0;nt<4;nt++) {
                        mma8(acc[mt][nt], ah[mt], bh[nt]);
                        mma8(acc[mt][nt], ah[mt], bl[nt]);
                        mma8(acc[mt][nt], al[mt], bh[nt]);
                    }
            }
            __syncthreads();
        }
#pragma unroll
        for (int mt=0;mt<4;mt++)
#pragma unroll
            for (int nt=0;nt<4;nt++) {
                int e = mt*16 + gid;
                int c = warp*32 + nt*8 + 2*tig;
                atomicAdd(&g_G[e*CC+c],       acc[mt][nt][0]);
                atomicAdd(&g_G[e*CC+c+1],     acc[mt][nt][1]);
                atomicAdd(&g_G[(e+8)*CC+c],   acc[mt][nt][2]);
                atomicAdd(&g_G[(e+8)*CC+c+1], acc[mt][nt][3]);
            }
        atomicAdd(&g_Wtb[tid], accWtb);
        if (tid < 64) { atomicAdd(&g_cnormd[tid], (double)accCN); atomicAdd(&g_bcd[tid], (double)accBC); }
        if (tid == 64) atomicAdd(&g_bbd, (double)accBB);
    } else {
        // ---- Y = X @ pw1^T  (hi/lo) ----
        float (*Xs)[36] = (float (*)[36])smp;
        float (*Bs)[36] = (float (*)[36])(smp + 9216);
        int yb = b - 256;
        int tok0 = (yb >> 2) * 64;
        int colgrp = yb & 3;
        const float* src = pw1 + (size_t)colgrp * 64 * CC;
        int wm = warp>>2, wn = warp&3;
        float acc[2][2][4];
#pragma unroll
        for (int mt=0;mt<2;mt++)
#pragma unroll
            for (int nt=0;nt<2;nt++)
#pragma unroll
                for (int q=0;q<4;q++) acc[mt][nt][q]=0.f;

        for (int ch=0; ch<8; ch++) {
            int kc = ch*32;
#pragma unroll
            for (int l=0;l<2;l++) {
                int idx = tid + l*256;
                int row = idx>>3, q = (idx&7)*4;
                float4 v = *(const float4*)(x + (size_t)(tok0+row)*CC + kc + q);
                Xs[row][q]=v.x; Xs[row][q+1]=v.y; Xs[row][q+2]=v.z; Xs[row][q+3]=v.w;
                float4 w = *(const float4*)(src + (size_t)row*CC + kc + q);
                Bs[row][q]=w.x; Bs[row][q+1]=w.y; Bs[row][q+2]=w.z; Bs[row][q+3]=w.w;
            }
            __syncthreads();
#pragma unroll
            for (int k8=0;k8<4;k8++) {
                int kb = k8*8;
                uint32_t ah[2][4], al[2][4], bh[2][2], bl[2][2];
#pragma unroll
                for (int mt=0;mt<2;mt++) {
                    int m0 = wm*32 + mt*16 + gid;
                    hilo(Xs[m0][kb+tig],     ah[mt][0], al[mt][0]);
                    hilo(Xs[m0+8][kb+tig],   ah[mt][1], al[mt][1]);
                    hilo(Xs[m0][kb+tig+4],   ah[mt][2], al[mt][2]);
                    hilo(Xs[m0+8][kb+tig+4], ah[mt][3], al[mt][3]);
                }
#pragma unroll
                for (int nt=0;nt<2;nt++) {
                    int nl = wn*16 + nt*8 + gid;
                    hilo(Bs[nl][kb+tig],   bh[nt][0], bl[nt][0]);
                    hilo(Bs[nl][kb+tig+4], bh[nt][1], bl[nt][1]);
                }
#pragma unroll
                for (int mt=0;mt<2;mt++)
#pragma unroll
                    for (int nt=0;nt<2;nt++) {
                        mma8(acc[mt][nt], ah[mt], bh[nt]);
                        mma8(acc[mt][nt], ah[mt], bl[nt]);
                        mma8(acc[mt][nt], al[mt], bh[nt]);
                    }
            }
            __syncthreads();
        }
#pragma unroll
        for (int mt=0;mt<2;mt++)
#pragma unroll
            for (int nt=0;nt<2;nt++) {
                int col = colgrp*64 + wn*16 + nt*8 + 2*tig;
#pragma unroll
                for (int rr=0;rr<2;rr++) {
                    int tok = tok0 + wm*32 + mt*16 + gid + rr*8;
                    g_Y[(size_t)tok*CC + col]   = acc[mt][nt][rr*2];
                    g_Y[(size_t)tok*CC + col+1] = acc[mt][nt][rr*2+1];
                }
            }
    }
}

// ================= phase 2: XM = X@M | xG+softmax+binning (hi/lo) =================
__global__ void __launch_bounds__(256) k_big2(const float* __restrict__ x,
                                              const float* __restrict__ u) {
    __shared__ __align__(16) char smp[36352];   // Xs 9216 + Bs 9216 + xgs 64*68*4=17408
    float (*Xs)[36] = (float (*)[36])smp;
    float (*Bs)[36] = (float (*)[36])(smp + 9216);
    float (*xgs)[68] = (float (*)[68])(smp + 18432);
    int b = blockIdx.x;
    int tid=threadIdx.x, warp=tid>>5, lane=tid&31, gid=lane>>2, tig=lane&3;
    int wm = warp>>2, wn = warp&3;
    int tok0, colgrp, mode;
    const float* src;
    if (b < 128) { tok0 = (b>>2)*64; colgrp = b&3; src = g_M + (size_t)colgrp*64*CC; mode=0; }
    else         { tok0 = (b-128)*64; colgrp = 0;  src = g_G; mode=1; }
    float acc[2][2][4];
#pragma unroll
    for (int mt=0;mt<2;mt++)
#pragma unroll
        for (int nt=0;nt<2;nt++)
#pragma unroll
            for (int q=0;q<4;q++) acc[mt][nt][q]=0.f;

    for (int ch=0; ch<8; ch++) {
        int kc = ch*32;
#pragma unroll
        for (int l=0;l<2;l++) {
            int idx = tid + l*256;
            int row = idx>>3, q = (idx&7)*4;
            float4 v = *(const float4*)(x + (size_t)(tok0+row)*CC + kc + q);
            Xs[row][q]=v.x; Xs[row][q+1]=v.y; Xs[row][q+2]=v.z; Xs[row][q+3]=v.w;
            float4 w = *(const float4*)(src + (size_t)row*CC + kc + q);
            Bs[row][q]=w.x; Bs[row][q+1]=w.y; Bs[row][q+2]=w.z; Bs[row][q+3]=w.w;
        }
        __syncthreads();
#pragma unroll
        for (int k8=0;k8<4;k8++) {
            int kb = k8*8;
            uint32_t ah[2][4], al[2][4], bh[2][2], bl[2][2];
#pragma unroll
            for (int mt=0;mt<2;mt++) {
                int m0 = wm*32 + mt*16 + gid;
                hilo(Xs[m0][kb+tig],     ah[mt][0], al[mt][0]);
                hilo(Xs[m0+8][kb+tig],   ah[mt][1], al[mt][1]);
                hilo(Xs[m0][kb+tig+4],   ah[mt][2], al[mt][2]);
                hilo(Xs[m0+8][kb+tig+4], ah[mt][3], al[mt][3]);
            }
#pragma unroll
            for (int nt=0;nt<2;nt++) {
                int nl = wn*16 + nt*8 + gid;
                hilo(Bs[nl][kb+tig],   bh[nt][0], bl[nt][0]);
                hilo(Bs[nl][kb+tig+4], bh[nt][1], bl[nt][1]);
            }
#pragma unroll
            for (int mt=0;mt<2;mt++)
#pragma unroll
                for (int nt=0;nt<2;nt++) {
                    mma8(acc[mt][nt], ah[mt], bh[nt]);
                    mma8(acc[mt][nt], ah[mt], bl[nt]);
                    mma8(acc[mt][nt], al[mt], bh[nt]);
                }
        }
        __syncthreads();
    }
    if (mode == 0) {
#pragma unroll
        for (int mt=0;mt<2;mt++)
#pragma unroll
            for (int nt=0;nt<2;nt++) {
                int col = wn*16 + nt*8 + 2*tig;
#pragma unroll
                for (int rr=0;rr<2;rr++) {
                    int tok = tok0 + wm*32 + mt*16 + gid + rr*8;
                    g_XM[(size_t)tok*CC + colgrp*64 + col]   = acc[mt][nt][rr*2];
                    g_XM[(size_t)tok*CC + colgrp*64 + col+1] = acc[mt][nt][rr*2+1];
                }
            }
        return;
    }
    // mode 1: stage xG tile, fused softmax/S1a/binning
#pragma unroll
    for (int mt=0;mt<2;mt++)
#pragma unroll
        for (int nt=0;nt<2;nt++) {
            int col = wn*16 + nt*8 + 2*tig;
#pragma unroll
            for (int rr=0;rr<2;rr++) {
                int lt = wm*32 + mt*16 + gid + rr*8;
                xgs[lt][col]   = acc[mt][nt][rr*2];
                xgs[lt][col+1] = acc[mt][nt][rr*2+1];
            }
        }
    __syncthreads();
    float cn0 = (float)g_cnormd[lane], cn1 = (float)g_cnormd[lane+32];
    float bc0 = (float)g_bcd[lane],    bc1 = (float)g_bcd[lane+32];
    float s1acc = 0.f;
    for (int k=0;k<8;k++) {
        int lt = warp*8 + k;
        size_t n = tok0 + lt;
        float xg0 = xgs[lt][lane]    + bc0;
        float xg1 = xgs[lt][lane+32] + bc1;
        float l0 = 2.f*xg0 - cn0 - logf(-logf(u[n*NE+lane]));
        float l1 = 2.f*xg1 - cn1 - logf(-logf(u[n*NE+lane+32]));
        float m = fmaxf(l0, l1);
#pragma unroll
        for (int o=16;o>=1;o>>=1) m = fmaxf(m, __shfl_xor_sync(0xffffffffu, m, o));
        float ex0 = expf(l0 - m), ex1 = expf(l1 - m);
        float S = ex0 + ex1;
#pragma unroll
        for (int o=16;o>=1;o>>=1) S += __shfl_xor_sync(0xffffffffu, S, o);
        float r0 = ex0 / S, r1 = ex1 / S;
        g_resp[n*NE+lane]    = r0;
        g_resp[n*NE+lane+32] = r1;
        float s1 = r0*xg0 + r1*xg1;
#pragma unroll
        for (int o=16;o>=1;o>>=1) s1 += __shfl_xor_sync(0xffffffffu, s1, o);
        if (lane == 0) s1acc += s1;
        if (r0 > 1e-9f) {
            int p = atomicAdd(&g_cnt[lane], 1);
            g_tokn[lane*NN+p] = (int)n; g_tokr[lane*NN+p] = r0;
        }
        if (r1 > 1e-9f) {
            int p = atomicAdd(&g_cnt[lane+32], 1);
            g_tokn[(lane+32)*NN+p] = (int)n; g_tokr[(lane+32)*NN+p] = r1;
        }
    }
    if (lane == 0) atomicAdd(&g_accd[1], (double)s1acc);
}

// ================= xWtb + S0 =================
__global__ void k_xw(const float* __restrict__ x) {
    int warp = threadIdx.x>>5, lane = threadIdx.x&31;
    int n = blockIdx.x*8 + warp;
    float qd=0.f, xw=0.f;
#pragma unroll
    for (int m=0;m<8;m++) {
        int idx = lane + m*32;
        float xv = x[(size_t)n*CC+idx];
        qd += xv * g_XM[(size_t)n*CC+idx];
        xw += xv * g_Wtb[idx];
    }
#pragma unroll
    for (int o=16;o>=1;o>>=1) {
        qd += __shfl_xor_sync(0xffffffffu, qd, o);
        xw += __shfl_xor_sync(0xffffffffu, xw, o);
    }
    if (lane == 0) {
        g_xWtb[n] = xw;
        atomicAdd(&g_accd[0], (double)(qd + 2.f*xw + (float)g_bbd));
    }
}

// ================= A=R^T X, B2=R^T XM, Q=R^T R (hi/lo), s, t =================
__global__ void __launch_bounds__(256) k_RX(const float* __restrict__ x) {
    __shared__ float Rs[32][68];
    __shared__ float Xs[32][260];
    __shared__ float Ms[32][260];
    __shared__ float tw[32];
    int tid=threadIdx.x, warp=tid>>5, lane=tid&31, gid=lane>>2, tig=lane&3;
    int n0 = blockIdx.x * 64;
    float accA[4][4][4], accB[4][4][4], accQ[4][4];
#pragma unroll
    for (int mt=0;mt<4;mt++) {
#pragma unroll
        for (int nt=0;nt<4;nt++)
#pragma unroll
            for (int q=0;q<4;q++) { accA[mt][nt][q]=0.f; accB[mt][nt][q]=0.f; }
#pragma unroll
        for (int q=0;q<4;q++) accQ[mt][q]=0.f;
    }
    float sp=0.f, tp=0.f;

    for (int cchunk=0; cchunk<2; cchunk++) {
        int nb = n0 + cchunk*32;
#pragma unroll
        for (int l=0;l<8;l++) {
            int idx = tid + l*256;
            int row = idx>>6, e2 = idx&63;
            Rs[row][e2] = g_resp[(size_t)(nb+row)*NE + e2];
        }
#pragma unroll
        for (int l=0;l<8;l++) {
            int idx = tid + l*256;
            int row = idx>>6, q = (idx&63)*4;
            float4 v = *(const float4*)(x + (size_t)(nb+row)*CC + q);
            Xs[row][q]=v.x; Xs[row][q+1]=v.y; Xs[row][q+2]=v.z; Xs[row][q+3]=v.w;
            float4 w = *(const float4*)(g_XM + (size_t)(nb+row)*CC + q);
            Ms[row][q]=w.x; Ms[row][q+1]=w.y; Ms[row][q+2]=w.z; Ms[row][q+3]=w.w;
        }
        if (tid < 32) tw[tid] = g_xWtb[nb+tid];
        __syncthreads();
        if (tid < 64) {
            for (int k=0;k<32;k++) { float rv = Rs[k][tid]; sp += rv; tp += rv*tw[k]; }
        }
#pragma unroll
        for (int k8=0;k8<4;k8++) {
            int kb = k8*8;
            uint32_t am[4][4], amh[4][4], aml[4][4];
#pragma unroll
            for (int mt=0;mt<4;mt++) {
                int m0 = mt*16;
                float v0 = Rs[kb+tig][m0+gid],   v1 = Rs[kb+tig][m0+gid+8];
                float v2 = Rs[kb+tig+4][m0+gid], v3 = Rs[kb+tig+4][m0+gid+8];
                am[mt][0]=fb(v0); am[mt][1]=fb(v1); am[mt][2]=fb(v2); am[mt][3]=fb(v3);
                hilo(v0, amh[mt][0], aml[mt][0]); hilo(v1, amh[mt][1], aml[mt][1]);
                hilo(v2, amh[mt][2], aml[mt][2]); hilo(v3, amh[mt][3], aml[mt][3]);
            }
#pragma unroll
            for (int nt=0;nt<4;nt++) {
                int c = warp*32 + nt*8 + gid;
                uint32_t bx[2] = { fb(Xs[kb+tig][c]), fb(Xs[kb+tig+4][c]) };
                uint32_t bm[2] = { fb(Ms[kb+tig][c]), fb(Ms[kb+tig+4][c]) };
#pragma unroll
                for (int mt=0;mt<4;mt++) { mma8(accA[mt][nt], am[mt], bx); mma8(accB[mt][nt], am[mt], bm); }
            }
            {
                int eq = warp*8 + gid;
                uint32_t bqh[2], bql[2];
                hilo(Rs[kb+tig][eq],   bqh[0], bql[0]);
                hilo(Rs[kb+tig+4][eq], bqh[1], bql[1]);
#pragma unroll
                for (int mt=0;mt<4;mt++) {
                    mma8(accQ[mt], amh[mt], bqh);
                    mma8(accQ[mt], amh[mt], bql);
                    mma8(accQ[mt], aml[mt], bqh);
                }
            }
        }
        __syncthreads();
    }
#pragma unroll
    for (int mt=0;mt<4;mt++) {
#pragma unroll
        for (int nt=0;nt<4;nt++) {
            int e = mt*16 + gid;
            int c = warp*32 + nt*8 + 2*tig;
            atomicAdd(&g_A[e*CC+c],        accA[mt][nt][0]);
            atomicAdd(&g_A[e*CC+c+1],      accA[mt][nt][1]);
            atomicAdd(&g_A[(e+8)*CC+c],    accA[mt][nt][2]);
            atomicAdd(&g_A[(e+8)*CC+c+1],  accA[mt][nt][3]);
            atomicAdd(&g_B2[e*CC+c],       accB[mt][nt][0]);
            atomicAdd(&g_B2[e*CC+c+1],     accB[mt][nt][1]);
            atomicAdd(&g_B2[(e+8)*CC+c],   accB[mt][nt][2]);
            atomicAdd(&g_B2[(e+8)*CC+c+1], accB[mt][nt][3]);
        }
        int e = mt*16 + gid;
        int eq = warp*8 + 2*tig;
        atomicAdd(&g_Q[e*NE+eq],       accQ[mt][0]);
        atomicAdd(&g_Q[e*NE+eq+1],     accQ[mt][1]);
        atomicAdd(&g_Q[(e+8)*NE+eq],   accQ[mt][2]);
        atomicAdd(&g_Q[(e+8)*NE+eq+1], accQ[mt][3]);
    }
    if (tid < 64) { atomicAdd(&g_s[tid], sp); atomicAdd(&g_t[tid], tp); }
}

// ================= Cnew = decay*Cents + gam*(A@W^T + s b^T) =================
__global__ void __launch_bounds__(256) k_cnew(const float* __restrict__ W,
                                              const float* __restrict__ cents,
                                              const float* __restrict__ bvec) {
    __shared__ float As[64][36];
    __shared__ float Ws[128][36];
    __shared__ float ss[64];
    int tid=threadIdx.x, warp=tid>>5, lane=tid&31, gid=lane>>2, tig=lane&3;
    int d0 = blockIdx.x * 128;
    if (tid < 64) ss[tid] = g_s[tid];
    float acc[4][2][4];
#pragma unroll
    for (int mt=0;mt<4;mt++)
#pragma unroll
        for (int nt=0;nt<2;nt++)
#pragma unroll
            for (int q=0;q<4;q++) acc[mt][nt][q]=0.f;

    for (int ch=0; ch<8; ch++) {
        int kc = ch*32;
#pragma unroll
        for (int l=0;l<2;l++) {
            int idx = tid + l*256;
            int row = idx>>3, q = (idx&7)*4;
            float4 v = *(const float4*)(g_A + (size_t)row*CC + kc + q);
            As[row][q]=v.x; As[row][q+1]=v.y; As[row][q+2]=v.z; As[row][q+3]=v.w;
        }
#pragma unroll
        for (int l=0;l<4;l++) {
            int idx = tid + l*256;
            int row = idx>>3, q = (idx&7)*4;
            float4 v = *(const float4*)(W + (size_t)(d0+row)*CC + kc + q);
            Ws[row][q]=v.x; Ws[row][q+1]=v.y; Ws[row][q+2]=v.z; Ws[row][q+3]=v.w;
        }
        __syncthreads();
#pragma unroll
        for (int k8=0;k8<4;k8++) {
            int kb = k8*8;
            uint32_t a[4][4], b[2][2];
#pragma unroll
            for (int mt=0;mt<4;mt++) {
                int e = mt*16 + gid;
                a[mt][0]=fb(As[e][kb+tig]);   a[mt][1]=fb(As[e+8][kb+tig]);
                a[mt][2]=fb(As[e][kb+tig+4]); a[mt][3]=fb(As[e+8][kb+tig+4]);
            }
#pragma unroll
            for (int nt=0;nt<2;nt++) {
                int dl = warp*16 + nt*8 + gid;
                b[nt][0]=fb(Ws[dl][kb+tig]); b[nt][1]=fb(Ws[dl][kb+tig+4]);
            }
#pragma unroll
            for (int mt=0;mt<4;mt++)
#pragma unroll
                for (int nt=0;nt<2;nt++) mma8(acc[mt][nt], a[mt], b[nt]);
        }
        __syncthreads();
    }
#pragma unroll
    for (int mt=0;mt<4;mt++)
#pragma unroll
        for (int nt=0;nt<2;nt++) {
            int e = mt*16 + gid;
            int d = d0 + warp*16 + nt*8 + 2*tig;
            float b0 = bvec[d], b1 = bvec[d+1];
            g_Cnew[(size_t)e*DD+d]       = DECAYv*cents[(size_t)e*DD+d]       + GAMv*(acc[mt][nt][0] + ss[e]*b0);
            g_Cnew[(size_t)e*DD+d+1]     = DECAYv*cents[(size_t)e*DD+d+1]     + GAMv*(acc[mt][nt][1] + ss[e]*b1);
            g_Cnew[(size_t)(e+8)*DD+d]   = DECAYv*cents[(size_t)(e+8)*DD+d]   + GAMv*(acc[mt][nt][2] + ss[e+8]*b0);
            g_Cnew[(size_t)(e+8)*DD+d+1] = DECAYv*cents[(size_t)(e+8)*DD+d+1] + GAMv*(acc[mt][nt][3] + ss[e+8]*b1);
        }
}

// ================= tail: H (hi/lo) | binned output GEMM =================
__global__ void __launch_bounds__(256) k_tail(float* __restrict__ out) {
    __shared__ __align__(16) char smp[70400];
    int b = blockIdx.x;
    int tid=threadIdx.x, warp=tid>>5, lane=tid&31, gid=lane>>2, tig=lane&3;
    if (b < 128) {
        float (*Cs)[36] = (float (*)[36])smp;
        int d0 = b * 512;
        float acc[4][4];
#pragma unroll
        for (int mt=0;mt<4;mt++)
#pragma unroll
            for (int q=0;q<4;q++) acc[mt][q]=0.f;

        for (int ch=0; ch<16; ch++) {
            int dbase = d0 + ch*32;
#pragma unroll
            for (int l=0;l<2;l++) {
                int idx = tid + l*256;
                int e = idx>>3, q = (idx&7)*4;
                float4 v = *(const float4*)(g_Cnew + (size_t)e*DD + dbase + q);
                Cs[e][q]=v.x; Cs[e][q+1]=v.y; Cs[e][q+2]=v.z; Cs[e][q+3]=v.w;
            }
            __syncthreads();
#pragma unroll
            for (int k8=0;k8<4;k8++) {
                int kb = k8*8;
                uint32_t ah[4][4], al[4][4], bh[2], bl[2];
#pragma unroll
                for (int mt=0;mt<4;mt++) {
                    int e = mt*16 + gid;
                    hilo(Cs[e][kb+tig],     ah[mt][0], al[mt][0]);
                    hilo(Cs[e+8][kb+tig],   ah[mt][1], al[mt][1]);
                    hilo(Cs[e][kb+tig+4],   ah[mt][2], al[mt][2]);
                    hilo(Cs[e+8][kb+tig+4], ah[mt][3], al[mt][3]);
                }
                int n0 = warp*8 + gid;
                hilo(Cs[n0][kb+tig],   bh[0], bl[0]);
                hilo(Cs[n0][kb+tig+4], bh[1], bl[1]);
#pragma unroll
                for (int mt=0;mt<4;mt++) {
                    mma8(acc[mt], ah[mt], bh);
                    mma8(acc[mt], ah[mt], bl);
                    mma8(acc[mt], al[mt], bh);
                }
            }
            __syncthreads();
        }
#pragma unroll
        for (int mt=0;mt<4;mt++) {
            int e = mt*16 + gid;
            int n = warp*8 + 2*tig;
            atomicAdd(&g_H[e*NE+n],       acc[mt][0]);
            atomicAdd(&g_H[e*NE+n+1],     acc[mt][1]);
            atomicAdd(&g_H[(e+8)*NE+n],   acc[mt][2]);
            atomicAdd(&g_H[(e+8)*NE+n+1], acc[mt][3]);
        }
    } else {
        int idx0 = b - 128;
        int e = idx0 & 63;
        int cnt = g_cnt[e];
        int a0 = (idx0 >> 6) * 32;
        if (a0 >= cnt) return;
        float (*ys)[260] = (float (*)[260])smp;
        float (*Cw)[36]  = (float (*)[36])(smp + 33280);
        int* stok        = (int*)(smp + 33280 + 36864);
        int wm = warp>>2, wn = warp&3;
#pragma unroll
        for (int l=0;l<8;l++) {
            int idx = tid + l*256;
            int row = idx >> 6, q = idx & 63;
            int aa = a0 + row;
            float r = 0.f; int n = 0;
            float4 v = make_float4(0.f,0.f,0.f,0.f);
            if (aa < cnt) {
                n = g_tokn[e*NN+aa]; r = g_tokr[e*NN+aa];
                v = *(const float4*)(g_Y + (size_t)n*CC + q*4);
            }
            ys[row][q*4]=r*v.x; ys[row][q*4+1]=r*v.y; ys[row][q*4+2]=r*v.z; ys[row][q*4+3]=r*v.w;
            if (q == 0) stok[row] = n;
        }
        __syncthreads();
        float acc[8][4];
#pragma unroll
        for (int nt=0;nt<8;nt++)
#pragma unroll
            for (int q=0;q<4;q++) acc[nt][q]=0.f;

        for (int ch=0; ch<8; ch++) {
            int kc = ch*32;
#pragma unroll
            for (int l=0;l<8;l++) {
                int idx = tid + l*256;
                int row = idx >> 3, q = (idx & 7)*4;
                float4 v = *(const float4*)(g_Cnew + (size_t)e*DD + (size_t)row*CC + kc + q);
                Cw[row][q]=v.x; Cw[row][q+1]=v.y; Cw[row][q+2]=v.z; Cw[row][q+3]=v.w;
            }
            __syncthreads();
#pragma unroll
            for (int k8=0;k8<4;k8++) {
                int kb = k8*8;
                uint32_t ah[4], al[4];
                int m0 = wm*16 + gid;
                hilo(ys[m0][kc+kb+tig],     ah[0], al[0]);
                hilo(ys[m0+8][kc+kb+tig],   ah[1], al[1]);
                hilo(ys[m0][kc+kb+tig+4],   ah[2], al[2]);
                hilo(ys[m0+8][kc+kb+tig+4], ah[3], al[3]);
#pragma unroll
                for (int nt=0;nt<8;nt++) {
                    int nc = wn*64 + nt*8 + gid;
                    uint32_t bh[2], bl[2];
                    hilo(Cw[nc][kb+tig],   bh[0], bl[0]);
                    hilo(Cw[nc][kb+tig+4], bh[1], bl[1]);
                    mma8(acc[nt], ah, bh);
                    mma8(acc[nt], ah, bl);
                    mma8(acc[nt], al, bh);
                }
            }
            __syncthreads();
        }
        int t0 = wm*16 + gid;
        int r0 = stok[t0], r1 = stok[t0+8];
#pragma unroll
        for (int nt=0;nt<8;nt++) {
            int i = wn*64 + nt*8 + 2*tig;
            atomicAdd(out + (size_t)r0*ROUT + i,   acc[nt][0]);
            atomicAdd(out + (size_t)r0*ROUT + i+1, acc[nt][1]);
            atomicAdd(out + (size_t)r1*ROUT + i,   acc[nt][2]);
            atomicAdd(out + (size_t)r1*ROUT + i+1, acc[nt][3]);
        }
    }
}

// ================= final: bias | loss =================
__global__ void k_fin(float* __restrict__ out, const float* __restrict__ pwB, int out_size) {
    int b = blockIdx.x, tid = threadIdx.x;
    if (b < NN) {
        out[(size_t)b*ROUT + tid] += pwB[tid];
        return;
    }
    __shared__ float red[256];
    __shared__ float lsh;
    float p = 0.f;
    for (int idx = tid; idx < NE*CC; idx += 256) {
        int e = idx >> 8, c = idx & 255;
        p += g_A[idx] * (g_B2[idx] + g_s[e]*g_Wtb[c]);
    }
    if (tid < NE) p += g_s[tid]*(g_t[tid] + (float)g_bbd*g_s[tid]);
    float q = 0.f;
    for (int idx = tid; idx < NE*NE; idx += 256) q += g_H[idx]*g_Q[idx];
    red[tid] = p; __syncthreads();
    for (int s=128;s>=1;s>>=1) { if (tid<s) red[tid]+=red[tid+s]; __syncthreads(); }
    float psum = red[0]; __syncthreads();
    red[tid] = q; __syncthreads();
    for (int s=128;s>=1;s>>=1) { if (tid<s) red[tid]+=red[tid+s]; __syncthreads(); }
    if (tid == 0) {
        float S1 = DECAYv*(float)g_accd[1] + GAMv*psum;
        lsh = COMMITv * ((float)g_accd[0] - 2.f*S1 + red[0]) / ((float)NN * (float)DD);
    }
    __syncthreads();
    for (int i = NN*ROUT + tid; i < out_size; i += 256) out[i] = lsh;
}

extern "C" void kernel_launch(void* const* d_in, const int* in_sizes, int n_in,
                              void* d_out, int out_size) {
    const float* x     = (const float*)d_in[0];
    const float* u     = (const float*)d_in[1];
    const float* W     = (const float*)d_in[2];
    const float* bvec  = (const float*)d_in[3];
    const float* pw1   = (const float*)d_in[4];
    const float* pwB   = (const float*)d_in[5];
    const float* cents = (const float*)d_in[6];
    float* out = (float*)d_out;

    k_zero<<<2048, 256>>>(out);
    k_p1<<<384, 256>>>(W, cents, bvec, x, pw1);
    k_big2<<<160, 256>>>(x, u);
    k_xw<<<256, 256>>>(x);
    k_RX<<<32, 256>>>(x);
    k_cnew<<<512, 256>>>(W, cents, bvec);
    k_tail<<<128 + 64*64, 256>>>(out);
    k_fin<<<NN + 1, 256>>>(out, pwB, out_size);
}